// round 7
// baseline (speedup 1.0000x reference)
#include <cuda_runtime.h>
#include <math.h>

#define B_SZ 512
#define T_SZ 512
#define IN_SZ 128
#define H_SZ 256
#define NB   128   // 8 batch-groups x 16 unit-slices; <=148 SMs => single wave

typedef unsigned long long ull;

// ---------------- scratch (static device globals; no allocation) ----------------
__device__ float g_h0[2][B_SZ * H_SZ];
__device__ float g_h1[2][B_SZ * H_SZ];
__device__ float g_o0[B_SZ * 256];
__device__ float g_o1[B_SZ * 256];
__device__ float g_z [B_SZ * 64];

// per-group barrier state (8 groups, 128B-padded; monotonic across replays)
__device__ unsigned g_gc[8 * 32];
__device__ volatile unsigned g_gp[8 * 32];

__device__ __forceinline__ float sigmoidf_(float x) { return 1.f / (1.f + expf(-x)); }

// packed f32x2 helpers (sm_103a FFMA2; PTX-only)
__device__ __forceinline__ ull pack2(float lo, float hi) {
    ull r; asm("mov.b64 %0, {%1, %2};" : "=l"(r) : "f"(lo), "f"(hi)); return r;
}
__device__ __forceinline__ float2 unpack2(ull p) {
    float2 v; asm("mov.b64 {%0, %1}, %2;" : "=f"(v.x), "=f"(v.y) : "l"(p)); return v;
}
#define FMA2(acc, a, b) asm("fma.rn.f32x2 %0, %1, %2, %0;" : "+l"(acc) : "l"(a), "l"(b))

__device__ __forceinline__ void prefetch_l2(const void* p) {
    asm volatile("prefetch.global.L2 [%0];" :: "l"(p));
}

// empty kernel: shifts ncu's capture index so the GRU kernel gets profiled
__global__ void dummy_kernel() {}

// Monotonic group barrier over the 16 blocks sharing bg. __threadfence (gpu scope)
// emits CCTL.IVALL on sm_103a -> reader L1 invalidated, peer h-writes visible.
__device__ __forceinline__ void group_bar(int bg, unsigned& ph) {
    __syncthreads();
    if (threadIdx.x == 0) {
        __threadfence();
        unsigned p = ph;
        if (atomicAdd(&g_gc[bg * 32], 1u) == p * 16u + 15u) {
            __threadfence();
            g_gp[bg * 32] = p + 1u;
        } else {
            while (g_gp[bg * 32] < p + 1u) { }
            __threadfence();
        }
    }
    __syncthreads();
    ph += 1u;
}

// ---- load one weight slice (48 rows = 3 gates x 16 units) into padded SMEM ----
template<int K>
__device__ __forceinline__ void load_w(const float* __restrict__ W, int us,
                                       float* dst, int tid) {
    const int n4 = 48 * K / 4;
    for (int idx = tid; idx < n4; idx += 256) {
        int r = idx / (K / 4), c4 = idx % (K / 4);
        int grow = (r >> 4) * 256 + us * 16 + (r & 15);
        *(float4*)(dst + r * (K + 4) + c4 * 4) =
            *(const float4*)(W + (long)grow * K + c4 * 4);
    }
}

// ---- activation chunk staging: 64 batch x 64 k ----
__device__ __forceinline__ void ld_chunk(float4* v, const float* __restrict__ src,
                                         long rs, int kc, int b0, int tid) {
    #pragma unroll
    for (int j = 0; j < 4; j++) {
        int idx = tid + j * 256;
        int r = idx >> 4, c4 = idx & 15;
        v[j] = *(const float4*)(src + (long)(b0 + r) * rs + kc + c4 * 4);
    }
}
__device__ __forceinline__ void st_chunk(float* dst, const float4* v, int tid) {
    #pragma unroll
    for (int j = 0; j < 4; j++) {
        int idx = tid + j * 256;
        int r = idx >> 4, c4 = idx & 15;
        *(float4*)(dst + r * 64 + c4 * 4) = v[j];
    }
}

// ---- compute one 64-K chunk: 3 gates x 4 batch, f32x2 K-packed accumulators ----
// FMA2s ordered gate-major: >=12 independent instructions between any
// same-accumulator pair (covers lat=4), 12 parallel dependency chains.
__device__ __forceinline__ void chunk_mm(const float* __restrict__ ws, int WP,
                                         const float* __restrict__ xb,
                                         int u_local, int bgrp,
                                         ull* a0, ull* a1, ull* a2) {
    const float* wp0 = ws + u_local * WP;
    const float* wp1 = wp0 + 16 * WP;
    const float* wp2 = wp1 + 16 * WP;
    const float* xp  = xb + bgrp * 256;   // 4 rows x 64
    #pragma unroll
    for (int k = 0; k < 64; k += 4) {
        const ulonglong2 w0 = *(const ulonglong2*)(wp0 + k);
        const ulonglong2 w1 = *(const ulonglong2*)(wp1 + k);
        const ulonglong2 w2 = *(const ulonglong2*)(wp2 + k);
        ull x0[4], x1[4];
        #pragma unroll
        for (int b = 0; b < 4; b++) {
            const ulonglong2 t = *(const ulonglong2*)(xp + b * 64 + k);
            x0[b] = t.x; x1[b] = t.y;
        }
        #pragma unroll
        for (int b = 0; b < 4; b++) FMA2(a0[b], x0[b], w0.x);
        #pragma unroll
        for (int b = 0; b < 4; b++) FMA2(a1[b], x0[b], w1.x);
        #pragma unroll
        for (int b = 0; b < 4; b++) FMA2(a2[b], x0[b], w2.x);
        #pragma unroll
        for (int b = 0; b < 4; b++) FMA2(a0[b], x1[b], w0.y);
        #pragma unroll
        for (int b = 0; b < 4; b++) FMA2(a1[b], x1[b], w1.y);
        #pragma unroll
        for (int b = 0; b < 4; b++) FMA2(a2[b], x1[b], w2.y);
    }
}

// ---- one GRU layer for one timestep (weights already in SMEM) ----
template<int K1, int WP1>
__device__ void gru_layer(
    const float* __restrict__ in1, long s1,            // ih input (64 x K1)
    const float* __restrict__ h_in,                    // (512,256)
    const float* wih, const float* whh,                // SMEM, padded
    float br, float bz, float bn, float bh,
    float* __restrict__ h_out, float* xbuf,
    int tid, int u_local, int bgrp, int u, int b0)
{
    ull ar[4], az[4], an_[4], ah[4];
    #pragma unroll
    for (int b = 0; b < 4; b++) {
        ar[b] = pack2(br, 0.f); az[b] = pack2(bz, 0.f);
        an_[b] = pack2(bn, 0.f); ah[b] = pack2(bh, 0.f);
    }

    constexpr int NC1 = K1 / 64;
    float4 v[4];
    ld_chunk(v, in1, s1, 0, b0, tid);
    int buf = 0;

    // ih phase
    #pragma unroll 1
    for (int c = 0; c < NC1; c++) {
        st_chunk(xbuf + buf * 4096, v, tid);
        __syncthreads();
        if (c + 1 < NC1) ld_chunk(v, in1, s1, (c + 1) * 64, b0, tid);
        else             ld_chunk(v, h_in, 256, 0, b0, tid);
        chunk_mm(wih + c * 64, WP1, xbuf + buf * 4096, u_local, bgrp, ar, az, an_);
        buf ^= 1;
    }
    // hh phase
    #pragma unroll 1
    for (int c = 0; c < 4; c++) {
        st_chunk(xbuf + buf * 4096, v, tid);
        __syncthreads();
        if (c + 1 < 4) ld_chunk(v, h_in, 256, (c + 1) * 64, b0, tid);
        chunk_mm(whh + c * 64, 260, xbuf + buf * 4096, u_local, bgrp, ar, az, ah);
        buf ^= 1;
    }

    #pragma unroll
    for (int b = 0; b < 4; b++) {
        int bb = bgrp * 4 + b;
        float2 vr = unpack2(ar[b]);
        float2 vz = unpack2(az[b]);
        float2 vn = unpack2(an_[b]);
        float2 vh = unpack2(ah[b]);
        float r  = sigmoidf_(vr.x + vr.y);
        float z  = sigmoidf_(vz.x + vz.y);
        float n  = tanhf((vn.x + vn.y) + r * (vh.x + vh.y));
        float hp = h_in[(long)(b0 + bb) * 256 + u];
        h_out[(long)(b0 + bb) * 256 + u] = (1.f - z) * n + z * hp;
    }
}

// ---------------- persistent GRU scan: weights SMEM-resident ----------------
__global__ void __launch_bounds__(256) gru_persistent(
    const float* __restrict__ x,
    const float* __restrict__ W0i, const float* __restrict__ W0h,
    const float* __restrict__ b0i, const float* __restrict__ b0h,
    const float* __restrict__ W1i, const float* __restrict__ W1h,
    const float* __restrict__ b1i, const float* __restrict__ b1h)
{
    extern __shared__ float sm[];
    float* w0i = sm;
    float* w0h = sm + 6336;
    float* w1i = sm + 18816;
    float* w1h = sm + 31296;
    float* xbuf = sm + 43776;

    const int tid     = threadIdx.x;
    const int bg      = blockIdx.x >> 4;   // 8 groups of 64 batch
    const int us      = blockIdx.x & 15;   // 16 unit-slices of 16 units
    const int u_local = tid & 15;
    const int u       = us * 16 + u_local;
    const int bgrp    = tid >> 4;          // 16 groups x 4 batch
    const int b0      = bg * 64;

    load_w<128>(W0i, us, w0i, tid);
    load_w<256>(W0h, us, w0h, tid);
    load_w<256>(W1i, us, w1i, tid);
    load_w<256>(W1h, us, w1h, tid);

    // zero initial hidden states (buffer 0): this block's share of its bg rows
    {
        int off = bg * 16384 + us * 1024 + tid * 4;
        float4 z = make_float4(0.f, 0.f, 0.f, 0.f);
        *(float4*)&g_h0[0][off] = z;
        *(float4*)&g_h1[0][off] = z;
    }
    unsigned ph = g_gp[bg * 32];
    group_bar(bg, ph);  // zeros visible in group; weights are block-local

    const float br0 = b0i[u]       + b0h[u];
    const float bz0 = b0i[256 + u] + b0h[256 + u];
    const float bn0 = b0i[512 + u];
    const float bh0 = b0h[512 + u];
    const float br1 = b1i[u]       + b1h[u];
    const float bz1 = b1i[256 + u] + b1h[256 + u];
    const float bn1 = b1i[512 + u];
    const float bh1 = b1h[512 + u];

    // prefetch line geometry for x(t+1): 64 rows x 4 lines (128B) each
    const int pr = tid >> 2, pc = (tid & 3) * 32;

    const long HB = (long)B_SZ * H_SZ;
    for (int t = 0; t < T_SZ; t++) {
        const int r = t & 1, w = r ^ 1;
        gru_layer<128, 132>(x + (long)t * IN_SZ, (long)T_SZ * IN_SZ,
                            &g_h0[0][0] + r * HB,
                            w0i, w0h, br0, bz0, bn0, bh0,
                            &g_h0[0][0] + w * HB, xbuf,
                            tid, u_local, bgrp, u, b0);
        if (t + 1 < T_SZ)   // x is read-only: safe to warm L2 across the barrier
            prefetch_l2(x + (long)(t + 1) * IN_SZ
                          + (long)(b0 + pr) * (T_SZ * IN_SZ) + pc);
        group_bar(bg, ph);   // peers' h0(t) ready
        gru_layer<256, 260>(&g_h0[0][0] + w * HB, 256L,
                            &g_h1[0][0] + r * HB,
                            w1i, w1h, br1, bz1, bn1, bh1,
                            &g_h1[0][0] + w * HB, xbuf,
                            tid, u_local, bgrp, u, b0);
    }
    // final h1 (t=511 odd -> w=0) lives in g_h1[0]
}

// ---------- LSTM heads: warp-per-2-outputs, lanes split K (coalesced) ----------
__global__ void __launch_bounds__(256) lstm_head_kernel(
    const float* __restrict__ s,
    const float* __restrict__ Wf, const float* __restrict__ bif, const float* __restrict__ bhf,
    const float* __restrict__ Wr, const float* __restrict__ bir, const float* __restrict__ bhr,
    float* __restrict__ out)
{
    __shared__ float ss[256];
    const int b = blockIdx.x, tid = threadIdx.x;
    const int warp = tid >> 5, lane = tid & 31;
    ss[tid] = s[b * 256 + tid];
    __syncthreads();

    #pragma unroll 1
    for (int oo = 0; oo < 32; oo += 2) {
        int idx = warp * 32 + oo;          // pair shares the same head
        int hd = idx >> 7, j0 = idx & 127, j1 = j0 + 1;
        const float* W  = hd ? Wr  : Wf;
        const float* bi = hd ? bir : bif;
        const float* bh = hd ? bhr : bhf;
        float di0 = 0.f, dg0 = 0.f, do0 = 0.f;
        float di1 = 0.f, dg1 = 0.f, do1 = 0.f;
        #pragma unroll
        for (int kk = 0; kk < 8; kk++) {
            int k = kk * 32 + lane;
            float sv = ss[k];
            di0 += sv * W[(long)j0 * 256 + k];
            di1 += sv * W[(long)j1 * 256 + k];
            dg0 += sv * W[(long)(256 + j0) * 256 + k];
            dg1 += sv * W[(long)(256 + j1) * 256 + k];
            do0 += sv * W[(long)(384 + j0) * 256 + k];
            do1 += sv * W[(long)(384 + j1) * 256 + k];
        }
        #pragma unroll
        for (int off = 16; off; off >>= 1) {
            di0 += __shfl_xor_sync(0xffffffffu, di0, off);
            di1 += __shfl_xor_sync(0xffffffffu, di1, off);
            dg0 += __shfl_xor_sync(0xffffffffu, dg0, off);
            dg1 += __shfl_xor_sync(0xffffffffu, dg1, off);
            do0 += __shfl_xor_sync(0xffffffffu, do0, off);
            do1 += __shfl_xor_sync(0xffffffffu, do1, off);
        }
        if (lane == 0) {
            di0 += bi[j0]       + bh[j0];
            dg0 += bi[256 + j0] + bh[256 + j0];
            do0 += bi[384 + j0] + bh[384 + j0];
            float c0 = sigmoidf_(di0) * tanhf(dg0);
            out[b * 256 + hd * 128 + j0] = sigmoidf_(do0) * tanhf(c0);
            di1 += bi[j1]       + bh[j1];
            dg1 += bi[256 + j1] + bh[256 + j1];
            do1 += bi[384 + j1] + bh[384 + j1];
            float c1 = sigmoidf_(di1) * tanhf(dg1);
            out[b * 256 + hd * 128 + j1] = sigmoidf_(do1) * tanhf(c1);
        }
    }
}

// ---------------- KAN: cubic B-spline basis (8 bases) ----------
__device__ __forceinline__ void bspl8(float x, float* bv) {
    const float h = 0.4f;
    float p[12];
    #pragma unroll
    for (int m = 0; m < 12; m++) p[m] = (float)(m - 3) * h - 1.0f;
    float b[11];
    #pragma unroll
    for (int j = 0; j < 11; j++) b[j] = (x >= p[j] && x < p[j + 1]) ? 1.f : 0.f;
    #pragma unroll
    for (int k = 1; k <= 3; k++) {
        #pragma unroll
        for (int j = 0; j < 11 - k; j++) {
            b[j] = (x - p[j]) / (p[j + k] - p[j]) * b[j]
                 + (p[j + k + 1] - x) / (p[j + k + 1] - p[j + 1]) * b[j + 1];
        }
    }
    #pragma unroll
    for (int j = 0; j < 8; j++) bv[j] = b[j];
}

// kan1: warp per 2 outputs in flight, lanes split the 256 inputs
__global__ void __launch_bounds__(256) kan1_kernel(
    const float* __restrict__ in,
    const float* __restrict__ base_w,
    const float* __restrict__ spline_w,
    const float* __restrict__ scaler,
    float* __restrict__ out)
{
    __shared__ float silu_s[256];
    __shared__ float bsp_s[256][9];   // pad 9: kills bank conflicts
    const int b = blockIdx.x, tid = threadIdx.x;
    const int warp = tid >> 5, lane = tid & 31;
    {
        float xv = in[b * 256 + tid];
        silu_s[tid] = xv / (1.f + expf(-xv));
        float bv[8]; bspl8(xv, bv);
        #pragma unroll
        for (int k = 0; k < 8; k++) bsp_s[tid][k] = bv[k];
    }
    __syncthreads();
    #pragma unroll 1
    for (int o = warp * 8; o < warp * 8 + 8; o += 2) {
        float accA = 0.f, accB = 0.f;
        #pragma unroll
        for (int ii = 0; ii < 8; ii++) {
            int i = ii * 32 + lane;
            float si = silu_s[i];
            accA += si * base_w[o * 256 + i];
            accB += si * base_w[(o + 1) * 256 + i];
            const float4* spA = (const float4*)(spline_w + ((long)o * 256 + i) * 8);
            const float4* spB = (const float4*)(spline_w + ((long)(o + 1) * 256 + i) * 8);
            float4 a0 = spA[0], a1 = spA[1], b0 = spB[0], b1 = spB[1];
            float bs0 = bsp_s[i][0], bs1 = bsp_s[i][1], bs2 = bsp_s[i][2], bs3 = bsp_s[i][3];
            float bs4 = bsp_s[i][4], bs5 = bsp_s[i][5], bs6 = bsp_s[i][6], bs7 = bsp_s[i][7];
            float sA = bs0 * a0.x + bs1 * a0.y + bs2 * a0.z + bs3 * a0.w
                     + bs4 * a1.x + bs5 * a1.y + bs6 * a1.z + bs7 * a1.w;
            float sB = bs0 * b0.x + bs1 * b0.y + bs2 * b0.z + bs3 * b0.w
                     + bs4 * b1.x + bs5 * b1.y + bs6 * b1.z + bs7 * b1.w;
            accA += scaler[o * 256 + i] * sA;
            accB += scaler[(o + 1) * 256 + i] * sB;
        }
        #pragma unroll
        for (int off = 16; off; off >>= 1) {
            accA += __shfl_xor_sync(0xffffffffu, accA, off);
            accB += __shfl_xor_sync(0xffffffffu, accB, off);
        }
        if (lane == 0) { out[b * 64 + o] = accA; out[b * 64 + o + 1] = accB; }
    }
}

// kan2: NIN=64, NOUT=10 (tiny)
__global__ void __launch_bounds__(64) kan2_kernel(
    const float* __restrict__ in,
    const float* __restrict__ base_w,
    const float* __restrict__ spline_w,
    const float* __restrict__ scaler,
    float* __restrict__ out)
{
    __shared__ float silu_s[64];
    __shared__ float bsp_s[64][9];
    const int b = blockIdx.x, tid = threadIdx.x;
    {
        float xv = in[b * 64 + tid];
        silu_s[tid] = xv / (1.f + expf(-xv));
        float bv[8]; bspl8(xv, bv);
        #pragma unroll
        for (int k = 0; k < 8; k++) bsp_s[tid][k] = bv[k];
    }
    __syncthreads();
    const int warp = tid >> 5, lane = tid & 31;
    if (warp < 2) {
        #pragma unroll 1
        for (int o = warp * 5; o < warp * 5 + 5; o++) {
            float acc = 0.f;
            #pragma unroll
            for (int ii = 0; ii < 2; ii++) {
                int i = ii * 32 + lane;
                acc += silu_s[i] * base_w[o * 64 + i];
                const float4* sp = (const float4*)(spline_w + ((long)o * 64 + i) * 8);
                float4 s0 = sp[0], s1 = sp[1];
                float s8 = bsp_s[i][0] * s0.x + bsp_s[i][1] * s0.y
                         + bsp_s[i][2] * s0.z + bsp_s[i][3] * s0.w
                         + bsp_s[i][4] * s1.x + bsp_s[i][5] * s1.y
                         + bsp_s[i][6] * s1.z + bsp_s[i][7] * s1.w;
                acc += scaler[o * 64 + i] * s8;
            }
            #pragma unroll
            for (int off = 16; off; off >>= 1) acc += __shfl_xor_sync(0xffffffffu, acc, off);
            if (lane == 0) out[b * 10 + o] = acc;
        }
    }
}

// ---------------- launch ----------------
extern "C" void kernel_launch(void* const* d_in, const int* in_sizes, int n_in,
                              void* d_out, int out_size) {
    const float* x        = (const float*)d_in[0];
    const float* g0_wih   = (const float*)d_in[1];
    const float* g0_whh   = (const float*)d_in[2];
    const float* g0_bih   = (const float*)d_in[3];
    const float* g0_bhh   = (const float*)d_in[4];
    const float* g1_wih   = (const float*)d_in[5];
    const float* g1_whh   = (const float*)d_in[6];
    const float* g1_bih   = (const float*)d_in[7];
    const float* g1_bhh   = (const float*)d_in[8];
    const float* lw_ih0   = (const float*)d_in[9];
    const float* lb_ih0   = (const float*)d_in[11];
    const float* lb_hh0   = (const float*)d_in[12];
    const float* lw_ih0r  = (const float*)d_in[13];
    const float* lb_ih0r  = (const float*)d_in[15];
    const float* lb_hh0r  = (const float*)d_in[16];
    const float* lw_ih1   = (const float*)d_in[17];
    const float* lb_ih1   = (const float*)d_in[19];
    const float* lb_hh1   = (const float*)d_in[20];
    const float* lw_ih1r  = (const float*)d_in[21];
    const float* lb_ih1r  = (const float*)d_in[23];
    const float* lb_hh1r  = (const float*)d_in[24];
    const float* kan1_base   = (const float*)d_in[25];
    const float* kan1_spline = (const float*)d_in[26];
    const float* kan1_scaler = (const float*)d_in[27];
    const float* kan2_base   = (const float*)d_in[28];
    const float* kan2_spline = (const float*)d_in[29];
    const float* kan2_scaler = (const float*)d_in[30];

    float *h1, *o0, *o1, *zz;
    cudaGetSymbolAddress((void**)&h1, g_h1);
    cudaGetSymbolAddress((void**)&o0, g_o0);
    cudaGetSymbolAddress((void**)&o1, g_o1);
    cudaGetSymbolAddress((void**)&zz, g_z);

    const int smem = (6336 + 12480 + 12480 + 12480 + 8192) * 4;  // 207,872 B
    cudaFuncSetAttribute(gru_persistent, cudaFuncAttributeMaxDynamicSharedMemorySize, smem);

    // index-shift dummies: put the GRU kernel under the ncu capture window
    dummy_kernel<<<1, 32>>>();
    dummy_kernel<<<1, 32>>>();
    dummy_kernel<<<1, 32>>>();

    gru_persistent<<<NB, 256, smem>>>(x,
                                      g0_wih, g0_whh, g0_bih, g0_bhh,
                                      g1_wih, g1_whh, g1_bih, g1_bhh);

    lstm_head_kernel<<<512, 256>>>(h1, lw_ih0, lb_ih0, lb_hh0,
                                   lw_ih0r, lb_ih0r, lb_hh0r, o0);
    lstm_head_kernel<<<512, 256>>>(o0, lw_ih1, lb_ih1, lb_hh1,
                                   lw_ih1r, lb_ih1r, lb_hh1r, o1);
    kan1_kernel<<<512, 256>>>(o1, kan1_base, kan1_spline, kan1_scaler, zz);
    kan2_kernel<<<512, 64>>>(zz, kan2_base, kan2_spline, kan2_scaler, (float*)d_out);
}